// round 1
// baseline (speedup 1.0000x reference)
#include <cuda_runtime.h>
#include <cuda_bf16.h>
#include <math.h>

#define NSTEPS 512
#define NFWD 40
#define DT_F (1.0f/512.0f)
#define OUT_PER_PATH (513*40)

// Precomputed-once tables (per launch, deterministic).
__device__ float  g_w[NSTEPS];    // Toeplitz kernel weights w[j]
__device__ float  g_K2[NSTEPS];   // inclusive prefix sum of w[j]^2
__device__ float4 g_nc[NFWD*3];   // folded per-forward constants

// ---------------------------------------------------------------------------
// Precompute kernel: 1 block, 512 threads.
// ---------------------------------------------------------------------------
__global__ void precompute_kernel(const float* __restrict__ F0,
                                  const float* __restrict__ alphas,
                                  const float* __restrict__ rhos,
                                  const float* __restrict__ nus,
                                  const float* __restrict__ tau,
                                  const float* __restrict__ L,
                                  const float* __restrict__ Lam) {
    __shared__ float s_warp[16];
    __shared__ float s_omega[NFWD];
    __shared__ float s_vs[NFWD];
    int tid  = threadIdx.x;
    int lane = tid & 31;
    int wid  = tid >> 5;

    // Toeplitz weights, computed in double (reference has fp32 cancellation here;
    // double keeps us strictly closer to the exact value).
    double scale = pow(1.0/512.0, -0.4) / 1.4891922488128171; // DT^ALPHA / Gamma(0.6)
    double j = (double)tid;
    float w = (float)((pow(j + 1.0, 0.6) - pow(j, 0.6)) / 0.6 * scale);
    g_w[tid] = w;

    // Inclusive block scan of w^2 -> K2[t]
    float v = w * w;
    #pragma unroll
    for (int o = 1; o < 32; o <<= 1) {
        float y = __shfl_up_sync(0xffffffffu, v, o);
        if (lane >= o) v += y;
    }
    if (lane == 31) s_warp[wid] = v;
    __syncthreads();
    if (wid == 0 && lane < 16) {
        float x = s_warp[lane];
        #pragma unroll
        for (int o = 1; o < 16; o <<= 1) {
            float y = __shfl_up_sync(0x0000ffffu, x, o);
            if (lane >= o) x += y;
        }
        s_warp[lane] = x;
    }
    __syncthreads();
    float off = (wid > 0) ? s_warp[wid - 1] : 0.0f;
    g_K2[tid] = v + off;

    // Per-forward folded constants
    if (tid < NFWD) {
        float f0 = F0[tid];
        float vs = alphas[tid] * sqrtf(fabsf(f0 + 0.02f));   // alphas * |F0+shift|^0.5
        s_vs[tid] = vs;
        s_omega[tid] = tau[tid] * vs / (1.0f + tau[tid] * f0);
    }
    __syncthreads();
    if (tid < NFWD) {
        int n = tid;
        float rho = rhos[n], nu = nus[n];
        float sr  = sqrtf(fmaxf(1.0f - rho * rho, 0.0f));
        float dot = 0.0f;
        #pragma unroll 8
        for (int jj = 0; jj < NFWD; jj++) dot += Lam[n*NFWD + jj] * s_omega[jj];
        float vs  = s_vs[n];
        float mu0 = -vs * dot;
        const float LOG2E = 1.4426950408889634f;
        float l0 = L[n*3+0], l1 = L[n*3+1], l2 = L[n*3+2];
        // exp(nu*fbm - vc*K2) == ex2( a.f  + cB.x * (-K2t) ), all folded with log2e
        g_nc[n*3+0] = make_float4(nu*rho*l0*LOG2E, nu*rho*l1*LOG2E,
                                  nu*rho*l2*LOG2E, nu*sr*LOG2E);
        g_nc[n*3+1] = make_float4(0.5f*nu*nu*DT_F*LOG2E,  // vc * log2e
                                  mu0*DT_F,               // mu0 * dt
                                  vs, 0.0f);
        g_nc[n*3+2] = make_float4(l0, l1, l2, F0[n]);     // raw loadings + F0
    }
}

// ---------------------------------------------------------------------------
// Packed fp32x2 helpers (sm_103a-only FFMA2 path)
// ---------------------------------------------------------------------------
__device__ __forceinline__ unsigned long long ffma2(unsigned long long a,
                                                    unsigned long long b,
                                                    unsigned long long c) {
    unsigned long long d;
    asm("fma.rn.f32x2 %0, %1, %2, %3;" : "=l"(d) : "l"(a), "l"(b), "l"(c));
    return d;
}
__device__ __forceinline__ unsigned long long splat2(float x) {
    unsigned long long r;
    asm("mov.b64 %0, {%1, %1};" : "=l"(r) : "f"(x));
    return r;
}

// ---------------------------------------------------------------------------
// Main Monte-Carlo kernel: one block per path, 512 threads (= 512 steps).
// ---------------------------------------------------------------------------
__global__ void __launch_bounds__(512, 2)
mc_kernel(const float4* __restrict__ dz, float* __restrict__ out) {
    extern __shared__ char smraw[];
    float4* dzS  = (float4*)smraw;          // [512] float4 : dz per step
    float4* ncS  = dzS + 512;               // [120] float4 : per-forward consts
    float*  wext = (float*)(ncS + 120);     // [544] : zero-padded weights, wext[32+j]=w[j]
    float*  buf  = wext + 544;              // [40][513] : dF, then cumsum

    int tid  = threadIdx.x;
    int p    = blockIdx.x;
    int wid  = tid >> 5;
    int lane = tid & 31;

    dzS[tid] = dz[(size_t)p * NSTEPS + tid];
    for (int i = tid; i < 544; i += 512) wext[i] = (i < 32) ? 0.0f : g_w[i - 32];
    if (tid < NFWD*3) ncS[tid] = g_nc[tid];
    __syncthreads();

    // Warp -> t-chunk assignment balancing the triangular load across SMSPs.
    const int CH[16] = {0,2,4,6, 15,13,11,9, 1,3,5,7, 14,12,10,8};
    int chunk = CH[wid];
    int t     = chunk * 32 + lane;
    int smax  = chunk * 32 + 32;   // warp-uniform loop bound

    // Causal convolution fbm4[t][0..3] = sum_{s<=t} w[t-s] * dz[s][0..3]
    unsigned long long a01 = 0ull, a23 = 0ull;
    const ulonglong2* dzU = (const ulonglong2*)dzS;
    const float* wp = wext + 32 + t;
    #pragma unroll 4
    for (int s = 0; s < smax; ++s) {
        ulonglong2 z = dzU[s];               // warp-uniform s -> broadcast LDS.128
        unsigned long long ww = splat2(wp[-s]); // coalesced LDS.32 (zero for s>t)
        a01 = ffma2(z.x, ww, a01);
        a23 = ffma2(z.y, ww, a23);
    }
    float2 f01 = *(float2*)&a01;
    float2 f23 = *(float2*)&a23;

    float nK2 = -g_K2[t];
    float4 zt = dzS[t];

    // Per-forward dF
    #pragma unroll 4
    for (int n = 0; n < NFWD; ++n) {
        float4 cA = ncS[n*3 + 0];
        float4 cB = ncS[n*3 + 1];
        float4 cC = ncS[n*3 + 2];
        float arg = fmaf(cA.x, f01.x,
                    fmaf(cA.y, f01.y,
                    fmaf(cA.z, f23.x,
                    fmaf(cA.w, f23.y, cB.x * nK2))));
        float uv;
        asm("ex2.approx.f32 %0, %1;" : "=f"(uv) : "f"(arg));
        float wrn = fmaf(cC.x, zt.x, fmaf(cC.y, zt.y, cC.z * zt.z));
        float dF  = uv * fmaf(cB.y, uv, cB.z * wrn);
        buf[n * 513 + t] = dF;               // consecutive t within warp: no conflicts
    }
    __syncthreads();

    // Cumsum over t per forward: warp-per-row shfl scans.
    for (int n = wid; n < NFWD; n += 16) {
        float carry = 0.0f;
        float* row = buf + n * 513;
        for (int c = 0; c < 16; ++c) {
            float x = row[c * 32 + lane];
            #pragma unroll
            for (int o = 1; o < 32; o <<= 1) {
                float y = __shfl_up_sync(0xffffffffu, x, o);
                if (lane >= o) x += y;
            }
            x += carry;
            row[c * 32 + lane] = x;
            carry = __shfl_sync(0xffffffffu, x, 31);
        }
    }
    __syncthreads();

    // Coalesced output: out[p][tt][n], tt=0 row is F0.
    float* outp = out + (size_t)p * OUT_PER_PATH;
    for (int i = tid; i < OUT_PER_PATH; i += 512) {
        int tt = i / 40;
        int n  = i - tt * 40;
        float v = ncS[n*3 + 2].w;            // F0[n]
        if (tt > 0) v += buf[n * 513 + tt - 1];
        outp[i] = v;
    }
}

// ---------------------------------------------------------------------------
// Launch
// ---------------------------------------------------------------------------
extern "C" void kernel_launch(void* const* d_in, const int* in_sizes, int n_in,
                              void* d_out, int out_size) {
    const float* dz     = (const float*)d_in[0];
    const float* F0     = (const float*)d_in[1];
    const float* alphas = (const float*)d_in[2];
    const float* rhos   = (const float*)d_in[3];
    const float* nus    = (const float*)d_in[4];
    const float* tau    = (const float*)d_in[5];
    const float* L      = (const float*)d_in[6];
    const float* Lam    = (const float*)d_in[7];
    float* out = (float*)d_out;

    const int SMEM = (512 + 120) * 16 + 544 * 4 + 40 * 513 * 4;  // 94368 B
    cudaFuncSetAttribute(mc_kernel, cudaFuncAttributeMaxDynamicSharedMemorySize, SMEM);

    precompute_kernel<<<1, 512>>>(F0, alphas, rhos, nus, tau, L, Lam);
    mc_kernel<<<2048, 512, SMEM>>>((const float4*)dz, out);
}

// round 12
// speedup vs baseline: 1.5206x; 1.5206x over previous
#include <cuda_runtime.h>
#include <cuda_fp16.h>
#include <math.h>

#define NSTEPS 512
#define NFWD 40
#define NJ    (2048*4)          // 8192 = paths * 4 factors
#define DT_F (1.0f/512.0f)
#define OUT_PER_PATH (513*40)
#define WD2_PAD 128
#define WD2_LEN (WD2_PAD + NSTEPS + 8)   // 648

// ---------------- device-global scratch (static; no allocation) -------------
__device__ float   g_w[NSTEPS];
__device__ float   g_K2[NSTEPS];
__device__ float4  g_nc[NFWD*3];
__device__ __half2 g_wd2[WD2_LEN];          // wd2[i] = (w[i-PAD], w[i-PAD-1])
__device__ __half  ZhT[NJ * NSTEPS];        // 8 MB: Z transposed, fp16, [j][s]
__device__ float   fbmG[NJ * NSTEPS];       // 16 MB: fbm result, [j][t]

__constant__ float4 c_nc[NFWD*3];

// ---------------------------------------------------------------------------
// Precompute: 1 block, 512 threads. Weights in double, K2 scan, constants.
// ---------------------------------------------------------------------------
__global__ void precompute_kernel(const float* __restrict__ F0,
                                  const float* __restrict__ alphas,
                                  const float* __restrict__ rhos,
                                  const float* __restrict__ nus,
                                  const float* __restrict__ tau,
                                  const float* __restrict__ L,
                                  const float* __restrict__ Lam) {
    __shared__ float s_w[NSTEPS];
    __shared__ float s_warp[16];
    __shared__ float s_omega[NFWD];
    __shared__ float s_vs[NFWD];
    int tid  = threadIdx.x;
    int lane = tid & 31;
    int wid  = tid >> 5;

    double scale = pow(1.0/512.0, -0.4) / 1.4891922488128171; // DT^ALPHA / Gamma(0.6)
    double j = (double)tid;
    float w = (float)((pow(j + 1.0, 0.6) - pow(j, 0.6)) / 0.6 * scale);
    g_w[tid] = w;
    s_w[tid] = w;

    // inclusive scan of w^2 -> K2[t]
    float v = w * w;
    #pragma unroll
    for (int o = 1; o < 32; o <<= 1) {
        float y = __shfl_up_sync(0xffffffffu, v, o);
        if (lane >= o) v += y;
    }
    if (lane == 31) s_warp[wid] = v;
    __syncthreads();
    if (wid == 0 && lane < 16) {
        float x = s_warp[lane];
        #pragma unroll
        for (int o = 1; o < 16; o <<= 1) {
            float y = __shfl_up_sync(0x0000ffffu, x, o);
            if (lane >= o) x += y;
        }
        s_warp[lane] = x;
    }
    __syncthreads();
    float off = (wid > 0) ? s_warp[wid - 1] : 0.0f;
    g_K2[tid] = v + off;

    // packed Toeplitz pairs for the mma B operand
    for (int i = tid; i < WD2_LEN; i += 512) {
        int k = i - WD2_PAD;
        float a = (k >= 0 && k < NSTEPS)     ? s_w[k]     : 0.0f;
        float b = (k-1 >= 0 && k-1 < NSTEPS) ? s_w[k - 1] : 0.0f;
        g_wd2[i] = __floats2half2_rn(a, b);   // .x = w[k], .y = w[k-1]
    }

    if (tid < NFWD) {
        float f0 = F0[tid];
        float vs = alphas[tid] * sqrtf(fabsf(f0 + 0.02f));
        s_vs[tid] = vs;
        s_omega[tid] = tau[tid] * vs / (1.0f + tau[tid] * f0);
    }
    __syncthreads();
    if (tid < NFWD) {
        int n = tid;
        float rho = rhos[n], nu = nus[n];
        float sr  = sqrtf(fmaxf(1.0f - rho * rho, 0.0f));
        float dot = 0.0f;
        #pragma unroll 8
        for (int jj = 0; jj < NFWD; jj++) dot += Lam[n*NFWD + jj] * s_omega[jj];
        float vs  = s_vs[n];
        float mu0 = -vs * dot;
        const float LOG2E = 1.4426950408889634f;
        float l0 = L[n*3+0], l1 = L[n*3+1], l2 = L[n*3+2];
        g_nc[n*3+0] = make_float4(nu*rho*l0*LOG2E, nu*rho*l1*LOG2E,
                                  nu*rho*l2*LOG2E, nu*sr*LOG2E);
        g_nc[n*3+1] = make_float4(0.5f*nu*nu*DT_F*LOG2E, mu0*DT_F, vs, 0.0f);
        g_nc[n*3+2] = make_float4(l0, l1, l2, F0[n]);
    }
}

// ---------------------------------------------------------------------------
// Convert dz (f32, [p][s][d]) -> ZhT (fp16, [j=p*4+d][s]); coalesced both ways.
// ---------------------------------------------------------------------------
__global__ void convert_kernel(const float4* __restrict__ dz) {
    int p = blockIdx.x;
    int s = threadIdx.x;
    float4 z = dz[(size_t)p * NSTEPS + s];
    __half* base = ZhT + ((size_t)p * 4) * NSTEPS + s;
    base[0*NSTEPS] = __float2half_rn(z.x);
    base[1*NSTEPS] = __float2half_rn(z.y);
    base[2*NSTEPS] = __float2half_rn(z.z);
    base[3*NSTEPS] = __float2half_rn(z.w);
}

// ---------------------------------------------------------------------------
// GEMM: fbmG[j][t] = sum_s ZhT[j][s] * w[t-s]   via mma.sync m16n8k16
// Block: 256 threads (8 warps, 4x2), tile M=128 (j) x N=128 (t).
// A (Z) fragments loaded directly from global; B (Toeplitz) from smem wd2.
// grid = (4 t-tiles, 64 j-tiles): t-tile fastest so each scheduling wave
// mixes light (triangular) and heavy tiles.
// ---------------------------------------------------------------------------
__device__ __forceinline__ void mma16816(float c[4], const unsigned a[4],
                                         unsigned b0, unsigned b1) {
    asm volatile(
        "mma.sync.aligned.m16n8k16.row.col.f32.f16.f16.f32 "
        "{%0,%1,%2,%3}, {%4,%5,%6,%7}, {%8,%9}, {%0,%1,%2,%3};\n"
        : "+f"(c[0]), "+f"(c[1]), "+f"(c[2]), "+f"(c[3])
        : "r"(a[0]), "r"(a[1]), "r"(a[2]), "r"(a[3]), "r"(b0), "r"(b1));
}

__global__ void __launch_bounds__(256)
gemm_kernel() {
    __shared__ unsigned s_wd2[WD2_LEN];   // half2 pairs as u32
    int tid  = threadIdx.x;
    int lane = tid & 31;
    int warp = tid >> 5;
    for (int i = tid; i < WD2_LEN; i += 256)
        s_wd2[i] = *((const unsigned*)g_wd2 + i);
    __syncthreads();

    int g  = lane >> 2;          // group row 0..7
    int tg = lane & 3;           // thread-in-group 0..3
    int warp_m = warp >> 1;      // 0..3
    int warp_n = warp & 1;       // 0..1

    int ttile = blockIdx.x;                    // 0..3  (fast dim)
    int jtile = blockIdx.y;                    // 0..63
    int j0 = jtile * 128 + warp_m * 32;        // j base for this warp
    int t0 = ttile * 128 + warp_n * 64;        // t base for this warp
    int nch = (ttile + 1) * 8;                 // k16 chunks (triangular bound)

    float c[2][8][4];
    #pragma unroll
    for (int mf = 0; mf < 2; mf++)
        #pragma unroll
        for (int nf = 0; nf < 8; nf++)
            #pragma unroll
            for (int q = 0; q < 4; q++) c[mf][nf][q] = 0.0f;

    const __half* Arow0 = ZhT + (size_t)(j0 + g) * NSTEPS + 2*tg;

    for (int ch = 0; ch < nch; ch++) {
        int s0 = ch << 4;
        unsigned a[2][4];
        #pragma unroll
        for (int mf = 0; mf < 2; mf++) {
            const __half* r0 = Arow0 + (size_t)(mf*16) * NSTEPS + s0;
            a[mf][0] = *(const unsigned*)(r0);
            a[mf][1] = *(const unsigned*)(r0 + 8*NSTEPS);
            a[mf][2] = *(const unsigned*)(r0 + 8);
            a[mf][3] = *(const unsigned*)(r0 + 8*NSTEPS + 8);
        }
        // B pairs: l[m] = wd2[PAD + t0 + g - s0 - 2tg + 8*(m-1)], m=0..8
        unsigned l[9];
        int bidx = WD2_PAD + t0 + g - s0 - 2*tg - 8;
        #pragma unroll
        for (int m = 0; m < 9; m++) l[m] = s_wd2[bidx + 8*m];

        #pragma unroll
        for (int nf = 0; nf < 8; nf++) {
            #pragma unroll
            for (int mf = 0; mf < 2; mf++)
                mma16816(c[mf][nf], a[mf], l[nf+1], l[nf]);
        }
    }

    // store: C rows = j, cols = t; pairs (c0,c1) contiguous in t
    #pragma unroll
    for (int mf = 0; mf < 2; mf++) {
        int jr = j0 + mf*16 + g;
        #pragma unroll
        for (int nf = 0; nf < 8; nf++) {
            int col = t0 + nf*8 + 2*tg;
            float2* p0 = (float2*)(fbmG + (size_t)jr * NSTEPS + col);
            float2* p1 = (float2*)(fbmG + (size_t)(jr+8) * NSTEPS + col);
            *p0 = make_float2(c[mf][nf][0], c[mf][nf][1]);
            *p1 = make_float2(c[mf][nf][2], c[mf][nf][3]);
        }
    }
}

// ---------------------------------------------------------------------------
// MC kernel: one block per path, 512 threads (= 512 steps).
// fbm comes precomputed from fbmG; constants from __constant__ memory.
// ---------------------------------------------------------------------------
__global__ void __launch_bounds__(512, 2)
mc_kernel(const float4* __restrict__ dz, float* __restrict__ out) {
    extern __shared__ float smraw[];
    float* buf  = smraw;                 // [40][513]
    float* sF0  = smraw + NFWD*513;      // [40]

    int tid  = threadIdx.x;
    int p    = blockIdx.x;
    int wid  = tid >> 5;
    int lane = tid & 31;
    int t    = tid;

    if (tid < NFWD) sF0[tid] = c_nc[tid*3+2].w;

    const float* fb = fbmG + ((size_t)p << 2) * NSTEPS + t;
    float fx = fb[0*NSTEPS];
    float fy = fb[1*NSTEPS];
    float fz = fb[2*NSTEPS];
    float fw = fb[3*NSTEPS];

    float4 zt  = dz[(size_t)p * NSTEPS + t];
    float  nK2 = -g_K2[t];

    #pragma unroll
    for (int n = 0; n < NFWD; ++n) {
        float4 cA = c_nc[n*3 + 0];
        float4 cB = c_nc[n*3 + 1];
        float4 cC = c_nc[n*3 + 2];
        float arg = fmaf(cA.x, fx,
                    fmaf(cA.y, fy,
                    fmaf(cA.z, fz,
                    fmaf(cA.w, fw, cB.x * nK2))));
        float uv;
        asm("ex2.approx.f32 %0, %1;" : "=f"(uv) : "f"(arg));
        float wrn = fmaf(cC.x, zt.x, fmaf(cC.y, zt.y, cC.z * zt.z));
        float dF  = uv * fmaf(cB.y, uv, cB.z * wrn);
        buf[n * 513 + t] = dF;
    }
    __syncthreads();

    // cumsum over t per forward: warp-per-row shfl scans
    for (int n = wid; n < NFWD; n += 16) {
        float carry = 0.0f;
        float* row = buf + n * 513;
        for (int cch = 0; cch < 16; ++cch) {
            float x = row[cch * 32 + lane];
            #pragma unroll
            for (int o = 1; o < 32; o <<= 1) {
                float y = __shfl_up_sync(0xffffffffu, x, o);
                if (lane >= o) x += y;
            }
            x += carry;
            row[cch * 32 + lane] = x;
            carry = __shfl_sync(0xffffffffu, x, 31);
        }
    }
    __syncthreads();

    // coalesced output: out[p][tt][n], tt=0 row is F0
    float* outp = out + (size_t)p * OUT_PER_PATH;
    for (int i = tid; i < OUT_PER_PATH; i += 512) {
        int tt = i / 40;
        int n  = i - tt * 40;
        float v = sF0[n];
        if (tt > 0) v += buf[n * 513 + tt - 1];
        outp[i] = v;
    }
}

// ---------------------------------------------------------------------------
// Launch
// ---------------------------------------------------------------------------
extern "C" void kernel_launch(void* const* d_in, const int* in_sizes, int n_in,
                              void* d_out, int out_size) {
    const float* dz     = (const float*)d_in[0];
    const float* F0     = (const float*)d_in[1];
    const float* alphas = (const float*)d_in[2];
    const float* rhos   = (const float*)d_in[3];
    const float* nus    = (const float*)d_in[4];
    const float* tau    = (const float*)d_in[5];
    const float* L      = (const float*)d_in[6];
    const float* Lam    = (const float*)d_in[7];
    float* out = (float*)d_out;

    precompute_kernel<<<1, 512>>>(F0, alphas, rhos, nus, tau, L, Lam);

    // copy folded constants into __constant__ (DtoD async; graph-capturable)
    void *src = nullptr, *dst = nullptr;
    cudaGetSymbolAddress(&src, g_nc);
    cudaGetSymbolAddress(&dst, c_nc);
    cudaMemcpyAsync(dst, src, sizeof(float4)*NFWD*3, cudaMemcpyDeviceToDevice, 0);

    convert_kernel<<<2048, 512>>>((const float4*)dz);

    dim3 ggrid(4, 64);
    gemm_kernel<<<ggrid, 256>>>();

    const int SMEM = (NFWD * 513 + NFWD) * 4;   // ~82.2 KB
    cudaFuncSetAttribute(mc_kernel, cudaFuncAttributeMaxDynamicSharedMemorySize, SMEM);
    mc_kernel<<<2048, 512, SMEM>>>((const float4*)dz, out);
}

// round 14
// speedup vs baseline: 1.5443x; 1.0156x over previous
#include <cuda_runtime.h>
#include <cuda_fp16.h>
#include <math.h>

#define NSTEPS 512
#define NFWD 40
#define NPAIR 20
#define NJ    (2048*4)
#define DT_F (1.0f/512.0f)
#define OUT_PER_PATH (513*40)
#define WD2_PAD 128
#define WD2_LEN (WD2_PAD + NSTEPS + 8)   // 648

typedef unsigned long long ull;

// ---------------- device-global scratch (static; no allocation) -------------
__device__ float   g_K2[NSTEPS];
__device__ float   g_F0s[NFWD];
__device__ ull     g_pk[NPAIR*10];          // pair-packed f32x2 constants
__device__ __half2 g_wd2[WD2_LEN];          // wd2[i] = (w[i-PAD], w[i-PAD-1])
__device__ __half  ZhT[NJ * NSTEPS];        // 8 MB: Z transposed, fp16, [j][s]
__device__ float   fbmG[NJ * NSTEPS];       // 16 MB: fbm result, [j][t]

// ---------------- packed f32x2 helpers --------------------------------------
__device__ __forceinline__ ull ffma2(ull a, ull b, ull c) {
    ull d; asm("fma.rn.f32x2 %0, %1, %2, %3;" : "=l"(d) : "l"(a), "l"(b), "l"(c));
    return d;
}
__device__ __forceinline__ ull fmul2(ull a, ull b) {
    ull d; asm("mul.rn.f32x2 %0, %1, %2;" : "=l"(d) : "l"(a), "l"(b));
    return d;
}
__device__ __forceinline__ ull splat2(float x) {
    ull r; asm("mov.b64 %0, {%1, %1};" : "=l"(r) : "f"(x)); return r;
}
__device__ __forceinline__ ull pack2(float lo, float hi) {
    ull r; asm("mov.b64 %0, {%1, %2};" : "=l"(r) : "f"(lo), "f"(hi)); return r;
}
__device__ __forceinline__ void unpack2(float& lo, float& hi, ull v) {
    asm("mov.b64 {%0, %1}, %2;" : "=f"(lo), "=f"(hi) : "l"(v));
}

// ---------------------------------------------------------------------------
// Precompute: 1 block, 512 threads.
// ---------------------------------------------------------------------------
__global__ void precompute_kernel(const float* __restrict__ F0,
                                  const float* __restrict__ alphas,
                                  const float* __restrict__ rhos,
                                  const float* __restrict__ nus,
                                  const float* __restrict__ tau,
                                  const float* __restrict__ L,
                                  const float* __restrict__ Lam) {
    __shared__ double s_pwd[NSTEPS+1];
    __shared__ float  s_w[NSTEPS];
    __shared__ float  s_warp[16];
    __shared__ float  s_omega[NFWD];
    __shared__ float  s_vs[NFWD];
    __shared__ float  s_cn[NFWD][10];
    int tid  = threadIdx.x;
    int lane = tid & 31;
    int wid  = tid >> 5;

    // one double pow per thread; diff in shared (double to avoid cancellation)
    if (tid == 0) s_pwd[0] = 0.0;
    s_pwd[tid+1] = pow((double)(tid+1), 0.6);
    __syncthreads();

    double scale = pow(1.0/512.0, -0.4) / 1.4891922488128171; // DT^ALPHA / Gamma(0.6)
    float w = (float)((s_pwd[tid+1] - s_pwd[tid]) / 0.6 * scale);
    s_w[tid] = w;

    // inclusive scan of w^2 -> K2[t]
    float v = w * w;
    #pragma unroll
    for (int o = 1; o < 32; o <<= 1) {
        float y = __shfl_up_sync(0xffffffffu, v, o);
        if (lane >= o) v += y;
    }
    if (lane == 31) s_warp[wid] = v;
    __syncthreads();
    if (wid == 0 && lane < 16) {
        float x = s_warp[lane];
        #pragma unroll
        for (int o = 1; o < 16; o <<= 1) {
            float y = __shfl_up_sync(0x0000ffffu, x, o);
            if (lane >= o) x += y;
        }
        s_warp[lane] = x;
    }
    __syncthreads();
    float off = (wid > 0) ? s_warp[wid - 1] : 0.0f;
    g_K2[tid] = v + off;

    // packed Toeplitz pairs for the mma B operand
    for (int i = tid; i < WD2_LEN; i += 512) {
        int k = i - WD2_PAD;
        float a = (k >= 0 && k < NSTEPS)     ? s_w[k]     : 0.0f;
        float b = (k-1 >= 0 && k-1 < NSTEPS) ? s_w[k - 1] : 0.0f;
        g_wd2[i] = __floats2half2_rn(a, b);
    }

    if (tid < NFWD) {
        float f0 = F0[tid];
        float vs = alphas[tid] * sqrtf(fabsf(f0 + 0.02f));
        s_vs[tid] = vs;
        s_omega[tid] = tau[tid] * vs / (1.0f + tau[tid] * f0);
        g_F0s[tid] = f0;
    }
    __syncthreads();
    if (tid < NFWD) {
        int n = tid;
        float rho = rhos[n], nu = nus[n];
        float sr  = sqrtf(fmaxf(1.0f - rho * rho, 0.0f));
        float dot = 0.0f;
        #pragma unroll 8
        for (int jj = 0; jj < NFWD; jj++) dot += Lam[n*NFWD + jj] * s_omega[jj];
        float vs  = s_vs[n];
        float mu0 = -vs * dot;
        const float LOG2E = 1.4426950408889634f;
        float l0 = L[n*3+0], l1 = L[n*3+1], l2 = L[n*3+2];
        s_cn[n][0] = nu*rho*l0*LOG2E;       // Ax
        s_cn[n][1] = nu*rho*l1*LOG2E;       // Ay
        s_cn[n][2] = nu*rho*l2*LOG2E;       // Az
        s_cn[n][3] = nu*sr*LOG2E;           // Aw
        s_cn[n][4] = 0.5f*nu*nu*DT_F*LOG2E; // Bx (vc*log2e)
        s_cn[n][5] = mu0*DT_F;              // By
        s_cn[n][6] = vs;                    // Bz
        s_cn[n][7] = l0;                    // Cx
        s_cn[n][8] = l1;                    // Cy
        s_cn[n][9] = l2;                    // Cz
    }
    __syncthreads();
    if (tid < NPAIR*10) {
        int pr = tid / 10, j = tid - pr*10;
        g_pk[tid] = pack2(s_cn[2*pr][j], s_cn[2*pr+1][j]);
    }
}

// ---------------------------------------------------------------------------
// Convert dz (f32, [p][s][d]) -> ZhT (fp16, [j=p*4+d][s]); coalesced both ways.
// ---------------------------------------------------------------------------
__global__ void convert_kernel(const float4* __restrict__ dz) {
    int p = blockIdx.x;
    int s = threadIdx.x;
    float4 z = dz[(size_t)p * NSTEPS + s];
    __half* base = ZhT + ((size_t)p * 4) * NSTEPS + s;
    base[0*NSTEPS] = __float2half_rn(z.x);
    base[1*NSTEPS] = __float2half_rn(z.y);
    base[2*NSTEPS] = __float2half_rn(z.z);
    base[3*NSTEPS] = __float2half_rn(z.w);
}

// ---------------------------------------------------------------------------
// GEMM: fbmG[j][t] = sum_s ZhT[j][s] * w[t-s]   via mma.sync m16n8k16
// (unchanged from round 12)
// ---------------------------------------------------------------------------
__device__ __forceinline__ void mma16816(float c[4], const unsigned a[4],
                                         unsigned b0, unsigned b1) {
    asm volatile(
        "mma.sync.aligned.m16n8k16.row.col.f32.f16.f16.f32 "
        "{%0,%1,%2,%3}, {%4,%5,%6,%7}, {%8,%9}, {%0,%1,%2,%3};\n"
        : "+f"(c[0]), "+f"(c[1]), "+f"(c[2]), "+f"(c[3])
        : "r"(a[0]), "r"(a[1]), "r"(a[2]), "r"(a[3]), "r"(b0), "r"(b1));
}

__global__ void __launch_bounds__(256)
gemm_kernel() {
    __shared__ unsigned s_wd2[WD2_LEN];
    int tid  = threadIdx.x;
    int lane = tid & 31;
    int warp = tid >> 5;
    for (int i = tid; i < WD2_LEN; i += 256)
        s_wd2[i] = *((const unsigned*)g_wd2 + i);
    __syncthreads();

    int g  = lane >> 2;
    int tg = lane & 3;
    int warp_m = warp >> 1;
    int warp_n = warp & 1;

    int ttile = blockIdx.x;                    // 0..3 (fast dim)
    int jtile = blockIdx.y;                    // 0..63
    int j0 = jtile * 128 + warp_m * 32;
    int t0 = ttile * 128 + warp_n * 64;
    int nch = (ttile + 1) * 8;                 // triangular bound

    float c[2][8][4];
    #pragma unroll
    for (int mf = 0; mf < 2; mf++)
        #pragma unroll
        for (int nf = 0; nf < 8; nf++)
            #pragma unroll
            for (int q = 0; q < 4; q++) c[mf][nf][q] = 0.0f;

    const __half* Arow0 = ZhT + (size_t)(j0 + g) * NSTEPS + 2*tg;

    for (int ch = 0; ch < nch; ch++) {
        int s0 = ch << 4;
        unsigned a[2][4];
        #pragma unroll
        for (int mf = 0; mf < 2; mf++) {
            const __half* r0 = Arow0 + (size_t)(mf*16) * NSTEPS + s0;
            a[mf][0] = *(const unsigned*)(r0);
            a[mf][1] = *(const unsigned*)(r0 + 8*NSTEPS);
            a[mf][2] = *(const unsigned*)(r0 + 8);
            a[mf][3] = *(const unsigned*)(r0 + 8*NSTEPS + 8);
        }
        unsigned l[9];
        int bidx = WD2_PAD + t0 + g - s0 - 2*tg - 8;
        #pragma unroll
        for (int m = 0; m < 9; m++) l[m] = s_wd2[bidx + 8*m];

        #pragma unroll
        for (int nf = 0; nf < 8; nf++) {
            #pragma unroll
            for (int mf = 0; mf < 2; mf++)
                mma16816(c[mf][nf], a[mf], l[nf+1], l[nf]);
        }
    }

    #pragma unroll
    for (int mf = 0; mf < 2; mf++) {
        int jr = j0 + mf*16 + g;
        #pragma unroll
        for (int nf = 0; nf < 8; nf++) {
            int col = t0 + nf*8 + 2*tg;
            float2* p0 = (float2*)(fbmG + (size_t)jr * NSTEPS + col);
            float2* p1 = (float2*)(fbmG + (size_t)(jr+8) * NSTEPS + col);
            *p0 = make_float2(c[mf][nf][0], c[mf][nf][1]);
            *p1 = make_float2(c[mf][nf][2], c[mf][nf][3]);
        }
    }
}

// ---------------------------------------------------------------------------
// MC kernel: one block per path, 512 threads. Pair-packed f32x2 dF, smem
// constants, F0 folded into scan carry, vectorized STG.128 output.
// buf layout: [pair][t][2]  (1026 floats per pair row)
// ---------------------------------------------------------------------------
__global__ void __launch_bounds__(512, 2)
mc_kernel(const float4* __restrict__ dz, float* __restrict__ out) {
    extern __shared__ float smraw[];
    float* buf = smraw;                                   // 20520 floats
    ull*   sPK = (ull*)(smraw + NPAIR*1026);              // 200 ull
    float* sF0 = (float*)(sPK + NPAIR*10);                // 40 floats

    int tid  = threadIdx.x;
    int p    = blockIdx.x;
    int wid  = tid >> 5;
    int lane = tid & 31;
    int t    = tid;

    if (tid < NPAIR*10) sPK[tid] = g_pk[tid];
    if (tid < NFWD)     sF0[tid] = g_F0s[tid];

    const float* fb = fbmG + ((size_t)p << 2) * NSTEPS + t;
    float fx = fb[0*NSTEPS];
    float fy = fb[1*NSTEPS];
    float fz = fb[2*NSTEPS];
    float fw = fb[3*NSTEPS];
    float4 zt  = dz[(size_t)p * NSTEPS + t];
    float  nK2 = -g_K2[t];

    ull sfx = splat2(fx), sfy = splat2(fy), sfz = splat2(fz), sfw = splat2(fw);
    ull snk = splat2(nK2);
    ull szx = splat2(zt.x), szy = splat2(zt.y), szz = splat2(zt.z);

    __syncthreads();

    // dF for 2 forwards per iteration (packed f32x2)
    float* myslot = buf + t*2;
    #pragma unroll 2
    for (int pp = 0; pp < NPAIR; ++pp) {
        const ull* pk = sPK + pp*10;
        ull arg = ffma2(pk[0], sfx,
                  ffma2(pk[1], sfy,
                  ffma2(pk[2], sfz,
                  ffma2(pk[3], sfw, fmul2(pk[4], snk)))));
        float a0, a1; unpack2(a0, a1, arg);
        float u0, u1;
        asm("ex2.approx.f32 %0, %1;" : "=f"(u0) : "f"(a0));
        asm("ex2.approx.f32 %0, %1;" : "=f"(u1) : "f"(a1));
        ull uv  = pack2(u0, u1);
        ull wrn = ffma2(pk[7], szx, ffma2(pk[8], szy, fmul2(pk[9], szz)));
        ull dF  = fmul2(uv, ffma2(pk[5], uv, fmul2(pk[6], wrn)));
        *(ull*)(myslot + pp*1026) = dF;
    }
    __syncthreads();

    // cumsum over t, two forwards per warp pass; carry seeded with F0
    for (int pp = wid; pp < NPAIR; pp += 16) {
        float c0 = sF0[2*pp], c1 = sF0[2*pp+1];
        float* row = buf + pp*1026 + lane*2;
        for (int ch = 0; ch < 16; ++ch) {
            float2 x = *(float2*)(row + ch*64);
            #pragma unroll
            for (int o = 1; o < 32; o <<= 1) {
                float y0 = __shfl_up_sync(0xffffffffu, x.x, o);
                float y1 = __shfl_up_sync(0xffffffffu, x.y, o);
                if (lane >= o) { x.x += y0; x.y += y1; }
            }
            x.x += c0; x.y += c1;
            *(float2*)(row + ch*64) = x;
            c0 = __shfl_sync(0xffffffffu, x.x, 31);
            c1 = __shfl_sync(0xffffffffu, x.y, 31);
        }
    }
    __syncthreads();

    // output: row 0 = F0; rows tt>=1 straight from scanned buf, STG.128
    float4* outp = (float4*)(out + (size_t)p * OUT_PER_PATH);
    if (tid < 10)
        outp[tid] = make_float4(sF0[4*tid], sF0[4*tid+1], sF0[4*tid+2], sF0[4*tid+3]);
    for (int q = 10 + tid; q < 5130; q += 512) {
        int gi = q * 4;
        float4 v;
        float* vv = (float*)&v;
        #pragma unroll
        for (int c = 0; c < 4; c++) {
            int idx = gi + c;
            int tt  = idx / 40;
            int n   = idx - tt * 40;
            vv[c] = buf[(n >> 1)*1026 + (tt - 1)*2 + (n & 1)];
        }
        outp[q] = v;
    }
}

// ---------------------------------------------------------------------------
// Launch (memcpy node removed)
// ---------------------------------------------------------------------------
extern "C" void kernel_launch(void* const* d_in, const int* in_sizes, int n_in,
                              void* d_out, int out_size) {
    const float* dz     = (const float*)d_in[0];
    const float* F0     = (const float*)d_in[1];
    const float* alphas = (const float*)d_in[2];
    const float* rhos   = (const float*)d_in[3];
    const float* nus    = (const float*)d_in[4];
    const float* tau    = (const float*)d_in[5];
    const float* L      = (const float*)d_in[6];
    const float* Lam    = (const float*)d_in[7];
    float* out = (float*)d_out;

    precompute_kernel<<<1, 512>>>(F0, alphas, rhos, nus, tau, L, Lam);
    convert_kernel<<<2048, 512>>>((const float4*)dz);

    dim3 ggrid(4, 64);
    gemm_kernel<<<ggrid, 256>>>();

    const int SMEM = NPAIR*1026*4 + NPAIR*10*8 + NFWD*4;   // 83840 B
    cudaFuncSetAttribute(mc_kernel, cudaFuncAttributeMaxDynamicSharedMemorySize, SMEM);
    mc_kernel<<<2048, 512, SMEM>>>((const float4*)dz, out);
}